// round 11
// baseline (speedup 1.0000x reference)
#include <cuda_runtime.h>
#include <cstddef>

#define TT 1024
#define BB 8
#define VV 32000
#define EE 32
#define HH 8
#define NROWS (TT*BB)      // 8192
#define VBLK  25           // grid.x of pass kernels
#define VITER 10           // outer iters; per iter a warp covers 16 n8-tiles = 128 v
#define LOG2E 1.4426950408889634f

// ---------------- scratch (device globals; no allocation) ----------------
__device__ float  g_xp[2*TT*BB*HH];      // [dir][t][b][h]  -log2e * (input proj + biases)
__device__ float  g_totalH[TT*2*BB*HH];  // [t][dir][b][j]  coalesced for the rnn store
__device__ float  g_partial[VBLK*NROWS]; // per v-block partial sum-of-exp (deterministic)
__device__ float  g_rowstat[NROWS];      // log(sum exp) per row
__device__ float  g_Wt[16*VV];           // tiled tf32 W (natural scale, pass2), 2 MB
__device__ float  g_Wt1[16*VV];          // tiled tf32 W * log2e (pass1), 2 MB
__device__ int    g_cnt[64];             // per row-block completion counters (self-reset)
// tile layout: vt (8 v): pos = vt*128 + n*16 + (k&3)*4 + (k>>2)
// thread (g=n, q) loads float4 {k=q, k=q+4, k=q+8, k=q+12} at vt*128 + g*16 + q*4

// tf32 round (rna)
__device__ __forceinline__ unsigned tf32_of(float x) {
    unsigned r;
    asm("cvt.rna.tf32.f32 %0, %1;" : "=r"(r) : "f"(x));
    return r;
}
__device__ __forceinline__ float ex2(float x) {
    float r; asm("ex2.approx.f32 %0, %1;" : "=f"(r) : "f"(x)); return r;
}
__device__ __forceinline__ float rcp(float x) {
    float r; asm("rcp.approx.f32 %0, %1;" : "=f"(r) : "f"(x)); return r;
}

// m16n8k8 tf32 mma, D += A*B (C aliased to D)
__device__ __forceinline__ void mma_tf32(float& d0, float& d1, float& d2, float& d3,
                                         unsigned a0, unsigned a1, unsigned a2, unsigned a3,
                                         unsigned b0, unsigned b1) {
    asm("mma.sync.aligned.m16n8k8.row.col.f32.tf32.tf32.f32 "
        "{%0,%1,%2,%3}, {%4,%5,%6,%7}, {%8,%9}, {%0,%1,%2,%3};"
        : "+f"(d0), "+f"(d1), "+f"(d2), "+f"(d3)
        : "r"(a0), "r"(a1), "r"(a2), "r"(a3), "r"(b0), "r"(b1));
}

// ---------------- kernel 0: W -> tiled tf32 (natural + log2e-scaled copies) ----
__global__ void k_prep(const float* __restrict__ Wo) {
    int v = blockIdx.x * 256 + threadIdx.x;   // grid.x = 125
    int k = blockIdx.y;                        // 16
    float x = __ldg(Wo + (size_t)k * VV + v);
    int pos = (v >> 3) * 128 + (v & 7) * 16 + (k & 3) * 4 + (k >> 2);
    g_Wt [pos] = __uint_as_float(tf32_of(x));
    g_Wt1[pos] = __uint_as_float(tf32_of(x * LOG2E));
}

// ---------------- kernel 1: embedding gather + x-projections ----------------
// stores xp' = -log2e * (e@Wx + bx + bh) so the rnn uses ex2 directly
__global__ void k_embed(const int* __restrict__ x, const float* __restrict__ emb,
                        const float* __restrict__ Wx1, const float* __restrict__ bx1,
                        const float* __restrict__ bh1,
                        const float* __restrict__ Wx2, const float* __restrict__ bx2,
                        const float* __restrict__ bh2) {
    int tid = blockIdx.x * blockDim.x + threadIdx.x;   // (t,b) flat
    if (tid >= NROWS) return;
    int idx = x[tid];
    const float4* em = (const float4*)(emb + (size_t)idx * EE);
    float e[EE];
    #pragma unroll
    for (int q = 0; q < 8; q++) {
        float4 v = __ldg(em + q);
        e[4*q] = v.x; e[4*q+1] = v.y; e[4*q+2] = v.z; e[4*q+3] = v.w;
    }
    #pragma unroll
    for (int j = 0; j < HH; j++) {
        float s1 = bx1[j] + bh1[j];
        float s2 = bx2[j] + bh2[j];
        #pragma unroll
        for (int k = 0; k < EE; k++) {
            s1 = fmaf(e[k], __ldg(Wx1 + k*HH + j), s1);
            s2 = fmaf(e[k], __ldg(Wx2 + k*HH + j), s2);
        }
        g_xp[tid*HH + j] = s1 * (-LOG2E);
        g_xp[TT*BB*HH + tid*HH + j] = s2 * (-LOG2E);
    }
}

// ---------------- kernel 2: the two sequential RNNs ----------------
// 2 blocks x 32 threads. lane = group*8 + j; each 8-lane group runs TWO
// independent chains (dir0,b) and (dir1,b) interleaved, so the two ~90-cycle
// dependency chains overlap in each other's stall shadow.
// Weights pre-scaled by -log2e so sigmoid = rcp(1 + ex2(z')).
// Emits h BEFORE the update (matches the reference scan).
__global__ void k_rnn(const float* __restrict__ Wh1, const float* __restrict__ Wh2) {
    int lane = threadIdx.x;
    int j = lane & 7;
    int b = blockIdx.x * 4 + (lane >> 3);   // batch id 0..7
    int grp = lane & ~7;                    // base lane of this group
    float wA[HH], wB[HH];
    #pragma unroll
    for (int k = 0; k < HH; k++) {
        wA[k] = __ldg(Wh1 + k*HH + j) * (-LOG2E);
        wB[k] = __ldg(Wh2 + k*HH + j) * (-LOG2E);
    }

    const float* xpA = g_xp;                 // dir 0, forward t
    const float* xpB = g_xp + TT*BB*HH;      // dir 1, backward t
    float hA = 0.f, hB = 0.f;

    // depth-4 prefetch rings
    float pfA[4], pfB[4];
    #pragma unroll
    for (int p = 0; p < 4; p++) {
        pfA[p] = __ldg(xpA + (p*BB + b) * HH + j);
        pfB[p] = __ldg(xpB + ((TT-1-p)*BB + b) * HH + j);
    }

    #pragma unroll 4
    for (int s = 0; s < TT; s++) {
        int slot = s & 3;
        float xvA = pfA[slot], xvB = pfB[slot];
        if (s + 4 < TT) {
            pfA[slot] = __ldg(xpA + ((s+4)*BB + b) * HH + j);
            pfB[slot] = __ldg(xpB + ((TT-5-s)*BB + b) * HH + j);
        }
        // emit pre-update hidden states: [t][dir][b][j]
        g_totalH[s*128 + b*8 + j] = hA;                   // dir0 at t=s
        g_totalH[(TT-1-s)*128 + 64 + b*8 + j] = hB;       // dir1 at t=TT-1-s

        // chain A
        float a0 = __shfl_sync(0xffffffffu, hA, grp + 0);
        float a1 = __shfl_sync(0xffffffffu, hA, grp + 1);
        float a2 = __shfl_sync(0xffffffffu, hA, grp + 2);
        float a3 = __shfl_sync(0xffffffffu, hA, grp + 3);
        float a4 = __shfl_sync(0xffffffffu, hA, grp + 4);
        float a5 = __shfl_sync(0xffffffffu, hA, grp + 5);
        float a6 = __shfl_sync(0xffffffffu, hA, grp + 6);
        float a7 = __shfl_sync(0xffffffffu, hA, grp + 7);
        // chain B (independent; overlaps A's latency)
        float c0 = __shfl_sync(0xffffffffu, hB, grp + 0);
        float c1 = __shfl_sync(0xffffffffu, hB, grp + 1);
        float c2 = __shfl_sync(0xffffffffu, hB, grp + 2);
        float c3 = __shfl_sync(0xffffffffu, hB, grp + 3);
        float c4 = __shfl_sync(0xffffffffu, hB, grp + 4);
        float c5 = __shfl_sync(0xffffffffu, hB, grp + 5);
        float c6 = __shfl_sync(0xffffffffu, hB, grp + 6);
        float c7 = __shfl_sync(0xffffffffu, hB, grp + 7);

        float tA0 = fmaf(a1, wA[1], a0 * wA[0]);
        float tA1 = fmaf(a3, wA[3], a2 * wA[2]);
        float tA2 = fmaf(a5, wA[5], a4 * wA[4]);
        float tA3 = fmaf(a7, wA[7], a6 * wA[6]);
        float tB0 = fmaf(c1, wB[1], c0 * wB[0]);
        float tB1 = fmaf(c3, wB[3], c2 * wB[2]);
        float tB2 = fmaf(c5, wB[5], c4 * wB[4]);
        float tB3 = fmaf(c7, wB[7], c6 * wB[6]);
        float zA = xvA + ((tA0 + tA1) + (tA2 + tA3));
        float zB = xvB + ((tB0 + tB1) + (tB2 + tB3));
        hA = rcp(1.f + ex2(zA));
        hB = rcp(1.f + ex2(zB));
    }
}

// ---------------- pass kernels: tf32 mma GEMM + softmax stats / output ----------------
// Warp owns 16 rows, block 256 = 128 rows, grid (VBLK, 64).
// Plain tf32 x tf32: 2 MMAs + 1 LDG.128 per warp-tile.
// PASS1 uses the log2e-scaled W copy so exp = bare EX2, and the last-arriving
// block per row-block folds the k_stat reduction (deterministic fixed-order sum).
template <bool PASS1>
__global__ __launch_bounds__(256) void k_pass(float* __restrict__ out) {
    int lane = threadIdx.x & 31, w = threadIdx.x >> 5;
    int g = lane >> 2, q = lane & 3;
    int rowBase = blockIdx.y * 128 + w * 16;

    // A fragments, loaded once. jj: row g+(jj&1)*8, col q+(jj>>1)*4
    unsigned ah[2][4];
    #pragma unroll
    for (int kt = 0; kt < 2; kt++) {
        #pragma unroll
        for (int jj = 0; jj < 4; jj++) {
            int r = g + (jj & 1) * 8;
            int k = kt * 8 + q + ((jj >> 1) ? 4 : 0);
            int grow = rowBase + r, t = grow >> 3, b = grow & 7;
            ah[kt][jj] = tf32_of(g_totalH[t*128 + (k >> 3)*64 + b*8 + (k & 7)]);
        }
    }

    float st0 = 0.f, st1 = 0.f;
    if (!PASS1) {
        st0 = g_rowstat[rowBase + g];
        st1 = g_rowstat[rowBase + g + 8];
    }

    float sum0 = 0.f, sum1 = 0.f;
    int vt0 = blockIdx.x * (VITER * 16);   // first v-tile index of this block

    const float* Wsrc = PASS1 ? g_Wt1 : g_Wt;
    const float4* Bt = (const float4*)(Wsrc + (size_t)vt0 * 128 + g * 16 + q * 4);
    float* op0;
    float* op1;
    if (!PASS1) {
        size_t vc = (size_t)vt0 * 8 + q * 2;
        op0 = out + (size_t)(rowBase + g    ) * VV + vc;
        op1 = out + (size_t)(rowBase + g + 8) * VV + vc;
    }

    for (int it = 0; it < VITER; it++) {
        #pragma unroll
        for (int nt = 0; nt < 16; nt++) {
            // B fragments: {k=q, q+4, q+8, q+12} at n=g in one LDG.128
            float4 B = __ldg(Bt);
            Bt += 32;                       // 128 floats = 32 float4 per tile
            unsigned b00 = __float_as_uint(B.x), b01 = __float_as_uint(B.y);
            unsigned b10 = __float_as_uint(B.z), b11 = __float_as_uint(B.w);

            float d0 = 0.f, d1 = 0.f, d2 = 0.f, d3 = 0.f;
            mma_tf32(d0,d1,d2,d3, ah[0][0],ah[0][1],ah[0][2],ah[0][3], b00,b01);
            mma_tf32(d0,d1,d2,d3, ah[1][0],ah[1][1],ah[1][2],ah[1][3], b10,b11);

            if (PASS1) {
                // d is log2e-scaled: e^z = 2^d
                sum0 += ex2(d0) + ex2(d1);
                sum1 += ex2(d2) + ex2(d3);
            } else {
                __stcs((float2*)op0, make_float2(d0 - st0, d1 - st0));
                __stcs((float2*)op1, make_float2(d2 - st1, d3 - st1));
                op0 += 8; op1 += 8;
            }
        }
    }

    if (PASS1) {
        // reduce across the 4 q-lanes sharing each row-group g
        sum0 += __shfl_xor_sync(0xffffffffu, sum0, 1);
        sum0 += __shfl_xor_sync(0xffffffffu, sum0, 2);
        sum1 += __shfl_xor_sync(0xffffffffu, sum1, 1);
        sum1 += __shfl_xor_sync(0xffffffffu, sum1, 2);
        if (q == 0) {
            float* p = g_partial + (size_t)blockIdx.x * NROWS + rowBase;
            p[g    ] = sum0;
            p[g + 8] = sum1;
        }

        // ---- fused stat: last block for this row-block reduces partials ----
        __shared__ bool isLast;
        __threadfence();                   // publish partials before counting
        __syncthreads();
        if (threadIdx.x == 0) {
            int old = atomicAdd(&g_cnt[blockIdx.y], 1);
            isLast = (old == VBLK - 1);
        }
        __syncthreads();
        if (isLast) {
            int r0 = blockIdx.y * 128;
            for (int r = threadIdx.x; r < 128; r += 256) {
                float s = 0.f;
                #pragma unroll
                for (int i = 0; i < VBLK; i++)
                    s += __ldcg(g_partial + (size_t)i * NROWS + r0 + r);
                g_rowstat[r0 + r] = logf(s);
            }
            if (threadIdx.x == 0) g_cnt[blockIdx.y] = 0;   // reset for next replay
        }
    }
}

// ---------------- launch ----------------
extern "C" void kernel_launch(void* const* d_in, const int* in_sizes, int n_in,
                              void* d_out, int out_size) {
    const int*   x   = (const int*)  d_in[0];
    const float* emb = (const float*)d_in[1];
    const float* Wx1 = (const float*)d_in[2];
    const float* bx1 = (const float*)d_in[3];
    const float* Wh1 = (const float*)d_in[4];
    const float* bh1 = (const float*)d_in[5];
    const float* Wx2 = (const float*)d_in[6];
    const float* bx2 = (const float*)d_in[7];
    const float* Wh2 = (const float*)d_in[8];
    const float* bh2 = (const float*)d_in[9];
    const float* Wo  = (const float*)d_in[10];
    float* out = (float*)d_out;

    dim3 gprep(125, 16);
    k_prep<<<gprep, 256>>>(Wo);
    k_embed<<<(NROWS + 255)/256, 256>>>(x, emb, Wx1, bx1, bh1, Wx2, bx2, bh2);
    k_rnn<<<2, 32>>>(Wh1, Wh2);
    dim3 grd(VBLK, NROWS/128), blk(256);
    k_pass<true ><<<grd, blk>>>(nullptr);
    k_pass<false><<<grd, blk>>>(out);
}

// round 12
// speedup vs baseline: 1.3049x; 1.3049x over previous
#include <cuda_runtime.h>
#include <cstddef>

#define TT 1024
#define BB 8
#define VV 32000
#define EE 32
#define HH 8
#define NROWS (TT*BB)      // 8192
#define VBLK  25           // grid.x of pass kernels
#define VITER 10           // outer iters; per iter a warp covers 8 tile-pairs = 128 v
#define LOG2E 1.4426950408889634f

// ---------------- scratch (device globals; no allocation) ----------------
__device__ float  g_xp[2*TT*BB*HH];      // [dir][t][b][h]  -log2e * (input proj + biases)
__device__ float  g_totalH[TT*2*BB*HH];  // [t][dir][b][j]  coalesced for the rnn store
__device__ float  g_partial[VBLK*NROWS]; // per v-block partial sum-of-exp (deterministic)
__device__ float  g_rowstat[NROWS];      // log(sum exp) per row
__device__ float  g_Wt[16*VV];           // tiled tf32 W (natural scale, pass2), 2 MB
__device__ float  g_Wt1[16*VV];          // tiled tf32 W * log2e (pass1), 2 MB
// pair-permuted tile layout: v-pair P = v>>4, u = v&15.
//   tile = 2P + ((u>>1)&1),  n = ((u>>2)<<1) | (u&1)
//   pos  = tile*128 + n*16 + (k&3)*4 + (k>>2)
// thread (g=n-group, q) then owns 4 CONSECUTIVE v = P*16 + 4q + {0,1,2,3}
// from the two tiles of a pair -> pass2 can STG.128.

// tf32 round (rna)
__device__ __forceinline__ unsigned tf32_of(float x) {
    unsigned r;
    asm("cvt.rna.tf32.f32 %0, %1;" : "=r"(r) : "f"(x));
    return r;
}
__device__ __forceinline__ float ex2(float x) {
    float r; asm("ex2.approx.f32 %0, %1;" : "=f"(r) : "f"(x)); return r;
}
__device__ __forceinline__ float rcp(float x) {
    float r; asm("rcp.approx.f32 %0, %1;" : "=f"(r) : "f"(x)); return r;
}

// m16n8k8 tf32 mma, D += A*B (C aliased to D)
__device__ __forceinline__ void mma_tf32(float& d0, float& d1, float& d2, float& d3,
                                         unsigned a0, unsigned a1, unsigned a2, unsigned a3,
                                         unsigned b0, unsigned b1) {
    asm("mma.sync.aligned.m16n8k8.row.col.f32.tf32.tf32.f32 "
        "{%0,%1,%2,%3}, {%4,%5,%6,%7}, {%8,%9}, {%0,%1,%2,%3};"
        : "+f"(d0), "+f"(d1), "+f"(d2), "+f"(d3)
        : "r"(a0), "r"(a1), "r"(a2), "r"(a3), "r"(b0), "r"(b1));
}

// ---------------- kernel 0: W -> pair-permuted tiled tf32 (2 copies) ----------
__global__ void k_prep(const float* __restrict__ Wo) {
    int v = blockIdx.x * 256 + threadIdx.x;   // grid.x = 125
    int k = blockIdx.y;                        // 16
    float x = __ldg(Wo + (size_t)k * VV + v);
    int P = v >> 4, u = v & 15;
    int tile = 2*P + ((u >> 1) & 1);
    int n = ((u >> 2) << 1) | (u & 1);
    int pos = tile*128 + n*16 + (k & 3)*4 + (k >> 2);
    g_Wt [pos] = __uint_as_float(tf32_of(x));
    g_Wt1[pos] = __uint_as_float(tf32_of(x * LOG2E));
}

// ---------------- kernel 1: embedding gather + x-projections ----------------
// stores xp' = -log2e * (e@Wx + bx + bh) so the rnn uses ex2 directly
__global__ void k_embed(const int* __restrict__ x, const float* __restrict__ emb,
                        const float* __restrict__ Wx1, const float* __restrict__ bx1,
                        const float* __restrict__ bh1,
                        const float* __restrict__ Wx2, const float* __restrict__ bx2,
                        const float* __restrict__ bh2) {
    int tid = blockIdx.x * blockDim.x + threadIdx.x;   // (t,b) flat
    if (tid >= NROWS) return;
    int idx = x[tid];
    const float4* em = (const float4*)(emb + (size_t)idx * EE);
    float e[EE];
    #pragma unroll
    for (int q = 0; q < 8; q++) {
        float4 v = __ldg(em + q);
        e[4*q] = v.x; e[4*q+1] = v.y; e[4*q+2] = v.z; e[4*q+3] = v.w;
    }
    #pragma unroll
    for (int j = 0; j < HH; j++) {
        float s1 = bx1[j] + bh1[j];
        float s2 = bx2[j] + bh2[j];
        #pragma unroll
        for (int k = 0; k < EE; k++) {
            s1 = fmaf(e[k], __ldg(Wx1 + k*HH + j), s1);
            s2 = fmaf(e[k], __ldg(Wx2 + k*HH + j), s2);
        }
        g_xp[tid*HH + j] = s1 * (-LOG2E);
        g_xp[TT*BB*HH + tid*HH + j] = s2 * (-LOG2E);
    }
}

// ---------------- kernel 2: the two sequential RNNs ----------------
// 16 blocks x 8 threads: ONE chain per warp (issue slots ~27/step << 85-cycle
// dependency chain -> latency-bound, no intra-warp issue contention).
// Weights pre-scaled by -log2e so sigmoid = rcp(1 + ex2(z')).
// Emits h BEFORE the update (matches the reference scan).
__global__ void k_rnn(const float* __restrict__ Wh1, const float* __restrict__ Wh2) {
    int j = threadIdx.x;                    // 0..7
    int c = blockIdx.x;                     // chain id 0..15
    int dir = c >> 3, b = c & 7;
    const float* Wh = dir ? Wh2 : Wh1;
    float w[HH];
    #pragma unroll
    for (int k = 0; k < HH; k++) w[k] = __ldg(Wh + k*HH + j) * (-LOG2E);

    const float* xp = g_xp + dir * (TT*BB*HH);
    float h = 0.f;

    // depth-4 prefetch ring
    float pf[4];
    #pragma unroll
    for (int p = 0; p < 4; p++) {
        int t = dir ? (TT - 1 - p) : p;
        pf[p] = __ldg(xp + (t*BB + b) * HH + j);
    }

    #pragma unroll 4
    for (int s = 0; s < TT; s++) {
        int slot = s & 3;
        float xv = pf[slot];
        if (s + 4 < TT) {
            int t4 = dir ? (TT - 1 - (s + 4)) : (s + 4);
            pf[slot] = __ldg(xp + (t4*BB + b) * HH + j);
        }
        int t = dir ? (TT - 1 - s) : s;
        // emit pre-update hidden state: [t][dir][b][j]
        g_totalH[t*128 + dir*64 + b*8 + j] = h;
        // z' = xv' + sum_k h_k * w'_kj   (already -log2e scaled)
        float h0 = __shfl_sync(0xffu, h, 0);
        float h1 = __shfl_sync(0xffu, h, 1);
        float h2 = __shfl_sync(0xffu, h, 2);
        float h3 = __shfl_sync(0xffu, h, 3);
        float h4 = __shfl_sync(0xffu, h, 4);
        float h5 = __shfl_sync(0xffu, h, 5);
        float h6 = __shfl_sync(0xffu, h, 6);
        float h7 = __shfl_sync(0xffu, h, 7);
        float t0 = fmaf(h1, w[1], h0 * w[0]);
        float t1 = fmaf(h3, w[3], h2 * w[2]);
        float t2 = fmaf(h5, w[5], h4 * w[4]);
        float t3 = fmaf(h7, w[7], h6 * w[6]);
        float z  = xv + ((t0 + t1) + (t2 + t3));
        h = rcp(1.f + ex2(z));              // sigmoid
    }
}

// ---------------- pass kernels: tf32 mma GEMM + softmax stats / output ----------------
// Warp owns 16 rows, block 256 = 128 rows, grid (VBLK, 64).
// Per tile-PAIR: 2 LDG.128 (B) + 4 MMAs; thread owns 4 consecutive v columns
// -> pass2 emits one STG.128 per row per pair.
// PASS1 uses the log2e-scaled W copy so exp = bare EX2.
template <bool PASS1>
__global__ __launch_bounds__(256) void k_pass(float* __restrict__ out) {
    int lane = threadIdx.x & 31, w = threadIdx.x >> 5;
    int g = lane >> 2, q = lane & 3;
    int rowBase = blockIdx.y * 128 + w * 16;

    // A fragments, loaded once. jj: row g+(jj&1)*8, col q+(jj>>1)*4
    unsigned ah[2][4];
    #pragma unroll
    for (int kt = 0; kt < 2; kt++) {
        #pragma unroll
        for (int jj = 0; jj < 4; jj++) {
            int r = g + (jj & 1) * 8;
            int k = kt * 8 + q + ((jj >> 1) ? 4 : 0);
            int grow = rowBase + r, t = grow >> 3, b = grow & 7;
            ah[kt][jj] = tf32_of(g_totalH[t*128 + (k >> 3)*64 + b*8 + (k & 7)]);
        }
    }

    float st0 = 0.f, st1 = 0.f;
    if (!PASS1) {
        st0 = g_rowstat[rowBase + g];
        st1 = g_rowstat[rowBase + g + 8];
    }

    float sum0 = 0.f, sum1 = 0.f;
    int vt0 = blockIdx.x * (VITER * 16);   // first v-tile index of this block

    const float* Wsrc = PASS1 ? g_Wt1 : g_Wt;
    const float4* Bt = (const float4*)(Wsrc + (size_t)vt0 * 128 + g * 16 + q * 4);
    float* op0;
    float* op1;
    if (!PASS1) {
        size_t vc = (size_t)vt0 * 8 + q * 4;   // P0*16 + 4q
        op0 = out + (size_t)(rowBase + g    ) * VV + vc;
        op1 = out + (size_t)(rowBase + g + 8) * VV + vc;
    }

    for (int it = 0; it < VITER; it++) {
        #pragma unroll
        for (int pr = 0; pr < 8; pr++) {       // 8 tile-pairs = 128 v per iter
            float4 B0 = __ldg(Bt);             // tile 2P
            float4 B1 = __ldg(Bt + 32);        // tile 2P+1
            Bt += 64;
            unsigned b000 = __float_as_uint(B0.x), b001 = __float_as_uint(B0.y);
            unsigned b010 = __float_as_uint(B0.z), b011 = __float_as_uint(B0.w);
            unsigned b100 = __float_as_uint(B1.x), b101 = __float_as_uint(B1.y);
            unsigned b110 = __float_as_uint(B1.z), b111 = __float_as_uint(B1.w);

            float e0 = 0.f, e1 = 0.f, e2 = 0.f, e3 = 0.f;   // tile0 frags
            mma_tf32(e0,e1,e2,e3, ah[0][0],ah[0][1],ah[0][2],ah[0][3], b000,b001);
            mma_tf32(e0,e1,e2,e3, ah[1][0],ah[1][1],ah[1][2],ah[1][3], b010,b011);
            float f0 = 0.f, f1 = 0.f, f2 = 0.f, f3 = 0.f;   // tile1 frags
            mma_tf32(f0,f1,f2,f3, ah[0][0],ah[0][1],ah[0][2],ah[0][3], b100,b101);
            mma_tf32(f0,f1,f2,f3, ah[1][0],ah[1][1],ah[1][2],ah[1][3], b110,b111);

            if (PASS1) {
                sum0 += (ex2(e0) + ex2(e1)) + (ex2(f0) + ex2(f1));
                sum1 += (ex2(e2) + ex2(e3)) + (ex2(f2) + ex2(f3));
            } else {
                // row g: consecutive v = {e0,e1,f0,f1}; row g+8: {e2,e3,f2,f3}
                *(float4*)op0 = make_float4(e0-st0, e1-st0, f0-st0, f1-st0);
                *(float4*)op1 = make_float4(e2-st1, e3-st1, f2-st1, f3-st1);
                op0 += 16; op1 += 16;
            }
        }
    }

    if (PASS1) {
        // reduce across the 4 q-lanes sharing each row-group g
        sum0 += __shfl_xor_sync(0xffffffffu, sum0, 1);
        sum0 += __shfl_xor_sync(0xffffffffu, sum0, 2);
        sum1 += __shfl_xor_sync(0xffffffffu, sum1, 1);
        sum1 += __shfl_xor_sync(0xffffffffu, sum1, 2);
        if (q == 0) {
            float* p = g_partial + (size_t)blockIdx.x * NROWS + rowBase;
            p[g    ] = sum0;
            p[g + 8] = sum1;
        }
    }
}

// ---------------- kernel: reduce partials -> log-sum-exp per row ----------------
__global__ void k_stat() {
    int r = blockIdx.x * blockDim.x + threadIdx.x;
    if (r >= NROWS) return;
    float s = 0.f;
    #pragma unroll
    for (int i = 0; i < VBLK; i++) s += g_partial[i * NROWS + r];
    g_rowstat[r] = logf(s);
}

// ---------------- launch ----------------
extern "C" void kernel_launch(void* const* d_in, const int* in_sizes, int n_in,
                              void* d_out, int out_size) {
    const int*   x   = (const int*)  d_in[0];
    const float* emb = (const float*)d_in[1];
    const float* Wx1 = (const float*)d_in[2];
    const float* bx1 = (const float*)d_in[3];
    const float* Wh1 = (const float*)d_in[4];
    const float* bh1 = (const float*)d_in[5];
    const float* Wx2 = (const float*)d_in[6];
    const float* bx2 = (const float*)d_in[7];
    const float* Wh2 = (const float*)d_in[8];
    const float* bh2 = (const float*)d_in[9];
    const float* Wo  = (const float*)d_in[10];
    float* out = (float*)d_out;

    dim3 gprep(125, 16);
    k_prep<<<gprep, 256>>>(Wo);
    k_embed<<<(NROWS + 255)/256, 256>>>(x, emb, Wx1, bx1, bh1, Wx2, bx2, bh2);
    k_rnn<<<16, 8>>>(Wh1, Wh2);
    dim3 grd(VBLK, NROWS/128), blk(256);
    k_pass<true ><<<grd, blk>>>(nullptr);
    k_stat<<<(NROWS + 255)/256, 256>>>();
    k_pass<false><<<grd, blk>>>(out);
}

// round 13
// speedup vs baseline: 1.4378x; 1.1019x over previous
#include <cuda_runtime.h>
#include <cstddef>

#define TT 1024
#define BB 8
#define VV 32000
#define EE 32
#define HH 8
#define NROWS (TT*BB)      // 8192
#define VBLK  25           // grid.x of the fused pass kernel
#define VITER 10           // outer iters; per iter a warp covers 8 tile-pairs = 128 v
#define LOG2E 1.4426950408889634f
#define LN2   0.6931471805599453f

// ---------------- scratch (device globals; no allocation) ----------------
__device__ float  g_xp[2*TT*BB*HH];      // [dir][t][b][h]  -log2e * (input proj + biases)
__device__ float  g_totalH[TT*2*BB*HH];  // [t][dir][b][j]  coalesced for the rnn store
__device__ float  g_partial[VBLK*NROWS]; // per v-block partial sum-of-exp (deterministic)
__device__ float  g_rowstat[NROWS];      // log(sum exp) per row (natural log)
__device__ float  g_Wt1[16*VV];          // tiled tf32 W * log2e, 2 MB (single copy)
__device__ int    g_cnt[64];             // per row-block completion counters
__device__ int    g_flag[64];            // per row-block rowstat-ready flags
// pair-permuted tile layout: v-pair P = v>>4, u = v&15.
//   tile = 2P + ((u>>1)&1),  n = ((u>>2)<<1) | (u&1)
//   pos  = tile*128 + n*16 + (k&3)*4 + (k>>2)
// thread (g=n-group, q) then owns 4 CONSECUTIVE v = P*16 + 4q + {0,1,2,3}
// from the two tiles of a pair -> phase B emits STG.128.

// tf32 round (rna)
__device__ __forceinline__ unsigned tf32_of(float x) {
    unsigned r;
    asm("cvt.rna.tf32.f32 %0, %1;" : "=r"(r) : "f"(x));
    return r;
}
__device__ __forceinline__ float ex2(float x) {
    float r; asm("ex2.approx.f32 %0, %1;" : "=f"(r) : "f"(x)); return r;
}
__device__ __forceinline__ float rcp(float x) {
    float r; asm("rcp.approx.f32 %0, %1;" : "=f"(r) : "f"(x)); return r;
}

// m16n8k8 tf32 mma, D += A*B (C aliased to D)
__device__ __forceinline__ void mma_tf32(float& d0, float& d1, float& d2, float& d3,
                                         unsigned a0, unsigned a1, unsigned a2, unsigned a3,
                                         unsigned b0, unsigned b1) {
    asm("mma.sync.aligned.m16n8k8.row.col.f32.tf32.tf32.f32 "
        "{%0,%1,%2,%3}, {%4,%5,%6,%7}, {%8,%9}, {%0,%1,%2,%3};"
        : "+f"(d0), "+f"(d1), "+f"(d2), "+f"(d3)
        : "r"(a0), "r"(a1), "r"(a2), "r"(a3), "r"(b0), "r"(b1));
}

// ---------------- kernel 0: W -> pair-permuted tiled tf32 (log2e-scaled) ------
__global__ void k_prep(const float* __restrict__ Wo) {
    int v = blockIdx.x * 256 + threadIdx.x;   // grid.x = 125
    int k = blockIdx.y;                        // 16
    float x = __ldg(Wo + (size_t)k * VV + v);
    int P = v >> 4, u = v & 15;
    int tile = 2*P + ((u >> 1) & 1);
    int n = ((u >> 2) << 1) | (u & 1);
    int pos = tile*128 + n*16 + (k & 3)*4 + (k >> 2);
    g_Wt1[pos] = __uint_as_float(tf32_of(x * LOG2E));
}

// ---------------- kernel 1: embedding gather + x-projections + flag reset -----
// stores xp' = -log2e * (e@Wx + bx + bh) so the rnn uses ex2 directly
__global__ void k_embed(const int* __restrict__ x, const float* __restrict__ emb,
                        const float* __restrict__ Wx1, const float* __restrict__ bx1,
                        const float* __restrict__ bh1,
                        const float* __restrict__ Wx2, const float* __restrict__ bx2,
                        const float* __restrict__ bh2) {
    int tid = blockIdx.x * blockDim.x + threadIdx.x;   // (t,b) flat
    if (blockIdx.x == 0 && threadIdx.x < 64) {         // reset sync state per replay
        g_cnt[threadIdx.x] = 0;
        g_flag[threadIdx.x] = 0;
    }
    if (tid >= NROWS) return;
    int idx = x[tid];
    const float4* em = (const float4*)(emb + (size_t)idx * EE);
    float e[EE];
    #pragma unroll
    for (int q = 0; q < 8; q++) {
        float4 v = __ldg(em + q);
        e[4*q] = v.x; e[4*q+1] = v.y; e[4*q+2] = v.z; e[4*q+3] = v.w;
    }
    #pragma unroll
    for (int j = 0; j < HH; j++) {
        float s1 = bx1[j] + bh1[j];
        float s2 = bx2[j] + bh2[j];
        #pragma unroll
        for (int k = 0; k < EE; k++) {
            s1 = fmaf(e[k], __ldg(Wx1 + k*HH + j), s1);
            s2 = fmaf(e[k], __ldg(Wx2 + k*HH + j), s2);
        }
        g_xp[tid*HH + j] = s1 * (-LOG2E);
        g_xp[TT*BB*HH + tid*HH + j] = s2 * (-LOG2E);
    }
}

// ---------------- kernel 2: the two sequential RNNs ----------------
// 16 blocks x 8 threads: one chain per warp (R12-proven config).
// Weights pre-scaled by -log2e so sigmoid = rcp(1 + ex2(z')).
// Emits h BEFORE the update (matches the reference scan).
__global__ void k_rnn(const float* __restrict__ Wh1, const float* __restrict__ Wh2) {
    int j = threadIdx.x;                    // 0..7
    int c = blockIdx.x;                     // chain id 0..15
    int dir = c >> 3, b = c & 7;
    const float* Wh = dir ? Wh2 : Wh1;
    float w[HH];
    #pragma unroll
    for (int k = 0; k < HH; k++) w[k] = __ldg(Wh + k*HH + j) * (-LOG2E);

    const float* xp = g_xp + dir * (TT*BB*HH);
    float h = 0.f;

    // depth-4 prefetch ring
    float pf[4];
    #pragma unroll
    for (int p = 0; p < 4; p++) {
        int t = dir ? (TT - 1 - p) : p;
        pf[p] = __ldg(xp + (t*BB + b) * HH + j);
    }

    #pragma unroll 4
    for (int s = 0; s < TT; s++) {
        int slot = s & 3;
        float xv = pf[slot];
        if (s + 4 < TT) {
            int t4 = dir ? (TT - 1 - (s + 4)) : (s + 4);
            pf[slot] = __ldg(xp + (t4*BB + b) * HH + j);
        }
        int t = dir ? (TT - 1 - s) : s;
        // emit pre-update hidden state: [t][dir][b][j]
        g_totalH[t*128 + dir*64 + b*8 + j] = h;
        // z' = xv' + sum_k h_k * w'_kj   (already -log2e scaled)
        float h0 = __shfl_sync(0xffu, h, 0);
        float h1 = __shfl_sync(0xffu, h, 1);
        float h2 = __shfl_sync(0xffu, h, 2);
        float h3 = __shfl_sync(0xffu, h, 3);
        float h4 = __shfl_sync(0xffu, h, 4);
        float h5 = __shfl_sync(0xffu, h, 5);
        float h6 = __shfl_sync(0xffu, h, 6);
        float h7 = __shfl_sync(0xffu, h, 7);
        float t0 = fmaf(h1, w[1], h0 * w[0]);
        float t1 = fmaf(h3, w[3], h2 * w[2]);
        float t2 = fmaf(h5, w[5], h4 * w[4]);
        float t3 = fmaf(h7, w[7], h6 * w[6]);
        float z  = xv + ((t0 + t1) + (t2 + t3));
        h = rcp(1.f + ex2(z));              // sigmoid
    }
}

// ---------------- fused pass: GEMM sums + stat + output in one kernel ----------
// Warp owns 16 rows, block 256 = 128 rows, grid (VBLK, 64).
// Phase A: log2-scale logits d -> sum 2^d, partials, per-row-block stat by the
// last-arriving block (deterministic fixed-order sum), flag release.
// Phase B (after spin on flag): recompute d from the SAME W tiles (L1/L2 hot),
// store  d*ln2 - st  as one STG.128 per row per tile-pair.
__global__ __launch_bounds__(256) void k_fused(float* __restrict__ out) {
    int lane = threadIdx.x & 31, w = threadIdx.x >> 5;
    int g = lane >> 2, q = lane & 3;
    int y = blockIdx.y;
    int rowBase = y * 128 + w * 16;

    // A fragments, loaded once. jj: row g+(jj&1)*8, col q+(jj>>1)*4
    unsigned ah[2][4];
    #pragma unroll
    for (int kt = 0; kt < 2; kt++) {
        #pragma unroll
        for (int jj = 0; jj < 4; jj++) {
            int r = g + (jj & 1) * 8;
            int k = kt * 8 + q + ((jj >> 1) ? 4 : 0);
            int grow = rowBase + r, t = grow >> 3, b = grow & 7;
            ah[kt][jj] = tf32_of(g_totalH[t*128 + (k >> 3)*64 + b*8 + (k & 7)]);
        }
    }

    int vt0 = blockIdx.x * (VITER * 16);   // first v-tile index of this block
    const float4* Bbase = (const float4*)(g_Wt1 + (size_t)vt0 * 128 + g * 16 + q * 4);

    // ---------------- phase A: sums ----------------
    {
        float sum0 = 0.f, sum1 = 0.f;
        const float4* Bt = Bbase;
        for (int it = 0; it < VITER; it++) {
            #pragma unroll
            for (int pr = 0; pr < 8; pr++) {       // 8 tile-pairs = 128 v per iter
                float4 B0 = __ldg(Bt);             // tile 2P
                float4 B1 = __ldg(Bt + 32);        // tile 2P+1
                Bt += 64;
                unsigned b000 = __float_as_uint(B0.x), b001 = __float_as_uint(B0.y);
                unsigned b010 = __float_as_uint(B0.z), b011 = __float_as_uint(B0.w);
                unsigned b100 = __float_as_uint(B1.x), b101 = __float_as_uint(B1.y);
                unsigned b110 = __float_as_uint(B1.z), b111 = __float_as_uint(B1.w);

                float e0 = 0.f, e1 = 0.f, e2 = 0.f, e3 = 0.f;
                mma_tf32(e0,e1,e2,e3, ah[0][0],ah[0][1],ah[0][2],ah[0][3], b000,b001);
                mma_tf32(e0,e1,e2,e3, ah[1][0],ah[1][1],ah[1][2],ah[1][3], b010,b011);
                float f0 = 0.f, f1 = 0.f, f2 = 0.f, f3 = 0.f;
                mma_tf32(f0,f1,f2,f3, ah[0][0],ah[0][1],ah[0][2],ah[0][3], b100,b101);
                mma_tf32(f0,f1,f2,f3, ah[1][0],ah[1][1],ah[1][2],ah[1][3], b110,b111);

                sum0 += (ex2(e0) + ex2(e1)) + (ex2(f0) + ex2(f1));
                sum1 += (ex2(e2) + ex2(e3)) + (ex2(f2) + ex2(f3));
            }
        }
        // reduce across the 4 q-lanes sharing each row-group g
        sum0 += __shfl_xor_sync(0xffffffffu, sum0, 1);
        sum0 += __shfl_xor_sync(0xffffffffu, sum0, 2);
        sum1 += __shfl_xor_sync(0xffffffffu, sum1, 1);
        sum1 += __shfl_xor_sync(0xffffffffu, sum1, 2);
        if (q == 0) {
            float* p = g_partial + (size_t)blockIdx.x * NROWS + rowBase;
            p[g    ] = sum0;
            p[g + 8] = sum1;
        }
    }

    // ---------------- stat by last-arriving block ----------------
    __shared__ bool isLast;
    __threadfence();                       // publish partials (release)
    __syncthreads();
    if (threadIdx.x == 0) {
        int old = atomicAdd(&g_cnt[y], 1);
        isLast = (old == VBLK - 1);
    }
    __syncthreads();
    if (isLast) {
        int r0 = y * 128;
        for (int r = threadIdx.x; r < 128; r += 256) {
            float s = 0.f;
            #pragma unroll
            for (int i = 0; i < VBLK; i++)
                s += __ldcg(g_partial + (size_t)i * NROWS + r0 + r);
            g_rowstat[r0 + r] = logf(s);
        }
        __threadfence();                   // publish rowstat before flag
        __syncthreads();
        if (threadIdx.x == 0) atomicExch(&g_flag[y], 1);
    }

    // ---------------- spin until rowstat ready ----------------
    if (threadIdx.x == 0) {
        while (atomicAdd(&g_flag[y], 0) == 0) __nanosleep(200);
    }
    __syncthreads();
    __threadfence();                       // acquire

    float st0 = __ldcg(g_rowstat + rowBase + g);
    float st1 = __ldcg(g_rowstat + rowBase + g + 8);

    // ---------------- phase B: outputs ----------------
    {
        const float4* Bt = Bbase;
        size_t vc = (size_t)vt0 * 8 + q * 4;   // P0*16 + 4q
        float* op0 = out + (size_t)(rowBase + g    ) * VV + vc;
        float* op1 = out + (size_t)(rowBase + g + 8) * VV + vc;

        for (int it = 0; it < VITER; it++) {
            #pragma unroll
            for (int pr = 0; pr < 8; pr++) {
                float4 B0 = __ldg(Bt);
                float4 B1 = __ldg(Bt + 32);
                Bt += 64;
                unsigned b000 = __float_as_uint(B0.x), b001 = __float_as_uint(B0.y);
                unsigned b010 = __float_as_uint(B0.z), b011 = __float_as_uint(B0.w);
                unsigned b100 = __float_as_uint(B1.x), b101 = __float_as_uint(B1.y);
                unsigned b110 = __float_as_uint(B1.z), b111 = __float_as_uint(B1.w);

                float e0 = 0.f, e1 = 0.f, e2 = 0.f, e3 = 0.f;
                mma_tf32(e0,e1,e2,e3, ah[0][0],ah[0][1],ah[0][2],ah[0][3], b000,b001);
                mma_tf32(e0,e1,e2,e3, ah[1][0],ah[1][1],ah[1][2],ah[1][3], b010,b011);
                float f0 = 0.f, f1 = 0.f, f2 = 0.f, f3 = 0.f;
                mma_tf32(f0,f1,f2,f3, ah[0][0],ah[0][1],ah[0][2],ah[0][3], b100,b101);
                mma_tf32(f0,f1,f2,f3, ah[1][0],ah[1][1],ah[1][2],ah[1][3], b110,b111);

                // natural logit = d * ln2 ; output = logit - logsumexp
                float4 o0 = make_float4(fmaf(e0, LN2, -st0), fmaf(e1, LN2, -st0),
                                        fmaf(f0, LN2, -st0), fmaf(f1, LN2, -st0));
                float4 o1 = make_float4(fmaf(e2, LN2, -st1), fmaf(e3, LN2, -st1),
                                        fmaf(f2, LN2, -st1), fmaf(f3, LN2, -st1));
                __stcs((float4*)op0, o0);
                __stcs((float4*)op1, o1);
                op0 += 16; op1 += 16;
            }
        }
    }
}

// ---------------- launch ----------------
extern "C" void kernel_launch(void* const* d_in, const int* in_sizes, int n_in,
                              void* d_out, int out_size) {
    const int*   x   = (const int*)  d_in[0];
    const float* emb = (const float*)d_in[1];
    const float* Wx1 = (const float*)d_in[2];
    const float* bx1 = (const float*)d_in[3];
    const float* Wh1 = (const float*)d_in[4];
    const float* bh1 = (const float*)d_in[5];
    const float* Wx2 = (const float*)d_in[6];
    const float* bx2 = (const float*)d_in[7];
    const float* Wh2 = (const float*)d_in[8];
    const float* bh2 = (const float*)d_in[9];
    const float* Wo  = (const float*)d_in[10];
    float* out = (float*)d_out;

    dim3 gprep(125, 16);
    k_prep<<<gprep, 256>>>(Wo);
    k_embed<<<(NROWS + 255)/256, 256>>>(x, emb, Wx1, bx1, bh1, Wx2, bx2, bh2);
    k_rnn<<<16, 8>>>(Wh1, Wh2);
    dim3 grd(VBLK, NROWS/128), blk(256);
    k_fused<<<grd, blk>>>(out);
}

// round 14
// speedup vs baseline: 1.5688x; 1.0911x over previous
#include <cuda_runtime.h>
#include <cstddef>

#define TT 1024
#define BB 8
#define VV 32000
#define EE 32
#define HH 8
#define NROWS (TT*BB)      // 8192
#define VBLK  25           // grid.x of the fused pass kernel
#define VITER 10           // outer iters; per iter a warp covers 8 tile-pairs = 128 v
#define LOG2E 1.4426950408889634f
#define LN2   0.6931471805599453f

// ---------------- scratch (device globals; no allocation) ----------------
__device__ float  g_xp[2*TT*BB*HH];      // [dir][t][b][h]  -log2e * (input proj + biases)
__device__ float  g_totalH[TT*2*BB*HH];  // [t][dir][b][j]  coalesced for the rnn store
__device__ float  g_partial[VBLK*NROWS]; // per v-block partial sum-of-exp (deterministic)
__device__ float  g_rowstat[NROWS];      // log(sum exp) per row (natural log)
__device__ float  g_Wt1[16*VV];          // tiled tf32 W * log2e, 2 MB (single copy)
__device__ int    g_cnt[64];             // per slice: phase-A completion counters
__device__ int    g_flag[64];            // per slice: rowstat-ready flags
__device__ int    g_sliceCnt[64];        // per slice: rnn chain completion (16 = ready)
// pair-permuted tile layout: v-pair P = v>>4, u = v&15.
//   tile = 2P + ((u>>1)&1),  n = ((u>>2)<<1) | (u&1)
//   pos  = tile*128 + n*16 + (k&3)*4 + (k>>2)
// thread (g=n-group, q) then owns 4 CONSECUTIVE v = P*16 + 4q + {0,1,2,3}
// from the two tiles of a pair -> phase B emits STG.128.

// tf32 round (rna)
__device__ __forceinline__ unsigned tf32_of(float x) {
    unsigned r;
    asm("cvt.rna.tf32.f32 %0, %1;" : "=r"(r) : "f"(x));
    return r;
}
__device__ __forceinline__ float ex2(float x) {
    float r; asm("ex2.approx.f32 %0, %1;" : "=f"(r) : "f"(x)); return r;
}
__device__ __forceinline__ float rcp(float x) {
    float r; asm("rcp.approx.f32 %0, %1;" : "=f"(r) : "f"(x)); return r;
}

// m16n8k8 tf32 mma, D += A*B (C aliased to D)
__device__ __forceinline__ void mma_tf32(float& d0, float& d1, float& d2, float& d3,
                                         unsigned a0, unsigned a1, unsigned a2, unsigned a3,
                                         unsigned b0, unsigned b1) {
    asm("mma.sync.aligned.m16n8k8.row.col.f32.tf32.tf32.f32 "
        "{%0,%1,%2,%3}, {%4,%5,%6,%7}, {%8,%9}, {%0,%1,%2,%3};"
        : "+f"(d0), "+f"(d1), "+f"(d2), "+f"(d3)
        : "r"(a0), "r"(a1), "r"(a2), "r"(a3), "r"(b0), "r"(b1));
}

// blockIdx.y -> t-slice permutation. Slice y ready at rnn step max(16y+15, 1023-16y):
// middle slices earliest. ylin=0 (contains the 16 rnn-carrier blocks) gets y=0
// (ready last); ylin>=1 get middle-out slices so the earliest-scheduled
// non-carrier blocks wait the least.
__device__ __forceinline__ int slice_of(int ylin) {
    if (ylin == 0) return 0;
    int j = ylin - 1;                       // 0..62
    return (j & 1) ? (32 - ((j + 1) >> 1)) : (32 + (j >> 1));  // 32,31,33,30,...,1,63
}

// ---------------- kernel 0: W -> pair-permuted tiled tf32 (log2e-scaled) ------
__global__ void k_prep(const float* __restrict__ Wo) {
    int v = blockIdx.x * 256 + threadIdx.x;   // grid.x = 125
    int k = blockIdx.y;                        // 16
    float x = __ldg(Wo + (size_t)k * VV + v);
    int P = v >> 4, u = v & 15;
    int tile = 2*P + ((u >> 1) & 1);
    int n = ((u >> 2) << 1) | (u & 1);
    int pos = tile*128 + n*16 + (k & 3)*4 + (k >> 2);
    g_Wt1[pos] = __uint_as_float(tf32_of(x * LOG2E));
}

// ---------------- kernel 1: embedding gather + x-projections + sync reset -----
// stores xp' = -log2e * (e@Wx + bx + bh) so the rnn uses ex2 directly
__global__ void k_embed(const int* __restrict__ x, const float* __restrict__ emb,
                        const float* __restrict__ Wx1, const float* __restrict__ bx1,
                        const float* __restrict__ bh1,
                        const float* __restrict__ Wx2, const float* __restrict__ bx2,
                        const float* __restrict__ bh2) {
    int tid = blockIdx.x * blockDim.x + threadIdx.x;   // (t,b) flat
    if (blockIdx.x == 0 && threadIdx.x < 64) {         // reset sync state per replay
        g_cnt[threadIdx.x] = 0;
        g_flag[threadIdx.x] = 0;
        g_sliceCnt[threadIdx.x] = 0;
    }
    if (tid >= NROWS) return;
    int idx = x[tid];
    const float4* em = (const float4*)(emb + (size_t)idx * EE);
    float e[EE];
    #pragma unroll
    for (int q = 0; q < 8; q++) {
        float4 v = __ldg(em + q);
        e[4*q] = v.x; e[4*q+1] = v.y; e[4*q+2] = v.z; e[4*q+3] = v.w;
    }
    #pragma unroll
    for (int j = 0; j < HH; j++) {
        float s1 = bx1[j] + bh1[j];
        float s2 = bx2[j] + bh2[j];
        #pragma unroll
        for (int k = 0; k < EE; k++) {
            s1 = fmaf(e[k], __ldg(Wx1 + k*HH + j), s1);
            s2 = fmaf(e[k], __ldg(Wx2 + k*HH + j), s2);
        }
        g_xp[tid*HH + j] = s1 * (-LOG2E);
        g_xp[TT*BB*HH + tid*HH + j] = s2 * (-LOG2E);
    }
}

// ---------------- rnn chain (runs inside carrier blocks of the fused kernel) ---
// Called by threads 0..7 of the block; chain id c in 0..15.
// Signals g_sliceCnt[t>>4] after finishing each 16-t slice (release ordering).
__device__ void run_chain(int c, int j,
                          const float* __restrict__ Wh1,
                          const float* __restrict__ Wh2) {
    int dir = c >> 3, b = c & 7;
    const float* Wh = dir ? Wh2 : Wh1;
    float w[HH];
    #pragma unroll
    for (int k = 0; k < HH; k++) w[k] = __ldg(Wh + k*HH + j) * (-LOG2E);

    const float* xp = g_xp + dir * (TT*BB*HH);
    float h = 0.f;

    // depth-4 prefetch ring
    float pf[4];
    #pragma unroll
    for (int p = 0; p < 4; p++) {
        int t = dir ? (TT - 1 - p) : p;
        pf[p] = __ldg(xp + (t*BB + b) * HH + j);
    }

    #pragma unroll 4
    for (int s = 0; s < TT; s++) {
        int slot = s & 3;
        float xv = pf[slot];
        if (s + 4 < TT) {
            int t4 = dir ? (TT - 1 - (s + 4)) : (s + 4);
            pf[slot] = __ldg(xp + (t4*BB + b) * HH + j);
        }
        int t = dir ? (TT - 1 - s) : s;
        // emit pre-update hidden state: [t][dir][b][j]
        g_totalH[t*128 + dir*64 + b*8 + j] = h;
        // slice boundary: dir0 ascending completes at t%16==15, dir1 at t%16==0
        if ((t & 15) == (dir ? 0 : 15)) {
            __syncwarp(0xffu);
            __threadfence();                 // release totalH stores
            if (j == 0) atomicAdd(&g_sliceCnt[t >> 4], 1);
        }
        // z' = xv' + sum_k h_k * w'_kj   (already -log2e scaled)
        float h0 = __shfl_sync(0xffu, h, 0);
        float h1 = __shfl_sync(0xffu, h, 1);
        float h2 = __shfl_sync(0xffu, h, 2);
        float h3 = __shfl_sync(0xffu, h, 3);
        float h4 = __shfl_sync(0xffu, h, 4);
        float h5 = __shfl_sync(0xffu, h, 5);
        float h6 = __shfl_sync(0xffu, h, 6);
        float h7 = __shfl_sync(0xffu, h, 7);
        float t0 = fmaf(h1, w[1], h0 * w[0]);
        float t1 = fmaf(h3, w[3], h2 * w[2]);
        float t2 = fmaf(h5, w[5], h4 * w[4]);
        float t3 = fmaf(h7, w[7], h6 * w[6]);
        float z  = xv + ((t0 + t1) + (t2 + t3));
        h = rcp(1.f + ex2(z));              // sigmoid
    }
}

// ---------------- fused kernel: rnn carriers + GEMM sums + stat + output -------
// Grid (VBLK, 64), block 256. Blocks (bx<16, ylin=0) first run one rnn chain
// each (warp 0, lanes 0..7; other warps park at __syncthreads). All blocks then
// spin until their t-slice of totalH is ready, and run the R13 flow:
// phase A (2^d sums -> partials -> last-block stat -> flag), spin, phase B
// (recompute, store d*ln2 - st with STG.128).
__global__ __launch_bounds__(256) void k_fused(float* __restrict__ out,
                                               const float* __restrict__ Wh1,
                                               const float* __restrict__ Wh2) {
    // ---------------- rnn carrier section ----------------
    if (blockIdx.y == 0 && blockIdx.x < 16) {
        if (threadIdx.x < 8)
            run_chain(blockIdx.x, threadIdx.x, Wh1, Wh2);
        __syncthreads();                   // park warps 1..7 while warp 0 chains
    }

    int lane = threadIdx.x & 31, w = threadIdx.x >> 5;
    int g = lane >> 2, q = lane & 3;
    int y = slice_of(blockIdx.y);
    int rowBase = y * 128 + w * 16;

    // ---------------- wait for this block's t-slice of totalH ----------------
    if (threadIdx.x == 0) {
        while (atomicAdd(&g_sliceCnt[y], 0) < 16) __nanosleep(100);
    }
    __syncthreads();
    __threadfence();                       // acquire totalH

    // A fragments, loaded once. jj: row g+(jj&1)*8, col q+(jj>>1)*4
    unsigned ah[2][4];
    #pragma unroll
    for (int kt = 0; kt < 2; kt++) {
        #pragma unroll
        for (int jj = 0; jj < 4; jj++) {
            int r = g + (jj & 1) * 8;
            int k = kt * 8 + q + ((jj >> 1) ? 4 : 0);
            int grow = rowBase + r, t = grow >> 3, b = grow & 7;
            ah[kt][jj] = tf32_of(g_totalH[t*128 + (k >> 3)*64 + b*8 + (k & 7)]);
        }
    }

    int vt0 = blockIdx.x * (VITER * 16);   // first v-tile index of this block
    const float4* Bbase = (const float4*)(g_Wt1 + (size_t)vt0 * 128 + g * 16 + q * 4);

    // ---------------- phase A: sums ----------------
    {
        float sum0 = 0.f, sum1 = 0.f;
        const float4* Bt = Bbase;
        for (int it = 0; it < VITER; it++) {
            #pragma unroll
            for (int pr = 0; pr < 8; pr++) {       // 8 tile-pairs = 128 v per iter
                float4 B0 = __ldg(Bt);             // tile 2P
                float4 B1 = __ldg(Bt + 32);        // tile 2P+1
                Bt += 64;
                unsigned b000 = __float_as_uint(B0.x), b001 = __float_as_uint(B0.y);
                unsigned b010 = __float_as_uint(B0.z), b011 = __float_as_uint(B0.w);
                unsigned b100 = __float_as_uint(B1.x), b101 = __float_as_uint(B1.y);
                unsigned b110 = __float_as_uint(B1.z), b111 = __float_as_uint(B1.w);

                float e0 = 0.f, e1 = 0.f, e2 = 0.f, e3 = 0.f;
                mma_tf32(e0,e1,e2,e3, ah[0][0],ah[0][1],ah[0][2],ah[0][3], b000,b001);
                mma_tf32(e0,e1,e2,e3, ah[1][0],ah[1][1],ah[1][2],ah[1][3], b010,b011);
                float f0 = 0.f, f1 = 0.f, f2 = 0.f, f3 = 0.f;
                mma_tf32(f0,f1,f2,f3, ah[0][0],ah[0][1],ah[0][2],ah[0][3], b100,b101);
                mma_tf32(f0,f1,f2,f3, ah[1][0],ah[1][1],ah[1][2],ah[1][3], b110,b111);

                sum0 += (ex2(e0) + ex2(e1)) + (ex2(f0) + ex2(f1));
                sum1 += (ex2(e2) + ex2(e3)) + (ex2(f2) + ex2(f3));
            }
        }
        // reduce across the 4 q-lanes sharing each row-group g
        sum0 += __shfl_xor_sync(0xffffffffu, sum0, 1);
        sum0 += __shfl_xor_sync(0xffffffffu, sum0, 2);
        sum1 += __shfl_xor_sync(0xffffffffu, sum1, 1);
        sum1 += __shfl_xor_sync(0xffffffffu, sum1, 2);
        if (q == 0) {
            float* p = g_partial + (size_t)blockIdx.x * NROWS + rowBase;
            p[g    ] = sum0;
            p[g + 8] = sum1;
        }
    }

    // ---------------- stat by last-arriving block of this slice ----------------
    __shared__ bool isLast;
    __threadfence();                       // publish partials (release)
    __syncthreads();
    if (threadIdx.x == 0) {
        int old = atomicAdd(&g_cnt[y], 1);
        isLast = (old == VBLK - 1);
    }
    __syncthreads();
    if (isLast) {
        int r0 = y * 128;
        for (int r = threadIdx.x; r < 128; r += 256) {
            float s = 0.f;
            #pragma unroll
            for (int i = 0; i < VBLK; i++)
                s += __ldcg(g_partial + (size_t)i * NROWS + r0 + r);
            g_rowstat[r0 + r] = logf(s);
        }
        __threadfence();                   // publish rowstat before flag
        __syncthreads();
        if (threadIdx.x == 0) atomicExch(&g_flag[y], 1);
    }

    // ---------------- spin until rowstat ready ----------------
    if (threadIdx.x == 0) {
        while (atomicAdd(&g_flag[y], 0) == 0) __nanosleep(200);
    }
    __syncthreads();
    __threadfence();                       // acquire

    float st0 = __ldcg(g_rowstat + rowBase + g);
    float st1 = __ldcg(g_rowstat + rowBase + g + 8);

    // ---------------- phase B: outputs ----------------
    {
        const float4* Bt = Bbase;
        size_t vc = (size_t)vt0 * 8 + q * 4;   // P0*16 + 4q
        float* op0 = out + (size_t)(rowBase + g    ) * VV + vc;
        float* op1 = out + (size_t)(rowBase + g + 8) * VV + vc;

        for (int it = 0; it < VITER; it++) {
            #pragma unroll
            for (int pr = 0; pr < 8; pr++) {
                float4 B0 = __ldg(Bt);
                float4 B1 = __ldg(Bt + 32);
                Bt += 64;
                unsigned b000 = __float_as_uint(B0.x), b001 = __float_as_uint(B0.y);
                unsigned b010 = __float_as_uint(B0.z), b011 = __float_as_uint(B0.w);
                unsigned b100 = __float_as_uint(B1.x), b101 = __float_as_uint(B1.y);
                unsigned b110 = __float_as_uint(B1.z), b111 = __float_as_uint(B1.w);

                float e0 = 0.f, e1 = 0.f, e2 = 0.f, e3 = 0.f;
                mma_tf32(e0,e1,e2,e3, ah[0][0],ah[0][1],ah[0][2],ah[0][3], b000,b001);
                mma_tf32(e0,e1,e2,e3, ah[1][0],ah[1][1],ah[1][2],ah[1][3], b010,b011);
                float f0 = 0.f, f1 = 0.f, f2 = 0.f, f3 = 0.f;
                mma_tf32(f0,f1,f2,f3, ah[0][0],ah[0][1],ah[0][2],ah[0][3], b100,b101);
                mma_tf32(f0,f1,f2,f3, ah[1][0],ah[1][1],ah[1][2],ah[1][3], b110,b111);

                // natural logit = d * ln2 ; output = logit - logsumexp
                float4 o0 = make_float4(fmaf(e0, LN2, -st0), fmaf(e1, LN2, -st0),
                                        fmaf(f0, LN2, -st0), fmaf(f1, LN2, -st0));
                float4 o1 = make_float4(fmaf(e2, LN2, -st1), fmaf(e3, LN2, -st1),
                                        fmaf(f2, LN2, -st1), fmaf(f3, LN2, -st1));
                __stcs((float4*)op0, o0);
                __stcs((float4*)op1, o1);
                op0 += 16; op1 += 16;
            }
        }
    }
}

// ---------------- launch ----------------
extern "C" void kernel_launch(void* const* d_in, const int* in_sizes, int n_in,
                              void* d_out, int out_size) {
    const int*   x   = (const int*)  d_in[0];
    const float* emb = (const float*)d_in[1];
    const float* Wx1 = (const float*)d_in[2];
    const float* bx1 = (const float*)d_in[3];
    const float* Wh1 = (const float*)d_in[4];
    const float* bh1 = (const float*)d_in[5];
    const float* Wx2 = (const float*)d_in[6];
    const float* bx2 = (const float*)d_in[7];
    const float* Wh2 = (const float*)d_in[8];
    const float* bh2 = (const float*)d_in[9];
    const float* Wo  = (const float*)d_in[10];
    float* out = (float*)d_out;

    dim3 gprep(125, 16);
    k_prep<<<gprep, 256>>>(Wo);
    k_embed<<<(NROWS + 255)/256, 256>>>(x, emb, Wx1, bx1, bh1, Wx2, bx2, bh2);
    dim3 grd(VBLK, NROWS/128), blk(256);
    k_fused<<<grd, blk>>>(out, Wh1, Wh2);
}

// round 15
// speedup vs baseline: 1.6215x; 1.0336x over previous
#include <cuda_runtime.h>
#include <cstddef>

#define TT 1024
#define BB 8
#define VV 32000
#define EE 32
#define HH 8
#define NROWS (TT*BB)      // 8192
#define VBLK  25           // grid.x of the fused pass kernel
#define VITER 10           // outer iters; per iter a warp covers 8 tile-pairs = 128 v
#define LOG2E 1.4426950408889634f
#define LN2   0.6931471805599453f

// ---------------- scratch (device globals; no allocation) ----------------
__device__ float  g_xp[2*TT*BB*HH];      // [dir][t][b][h]  -log2e * (input proj + biases)
__device__ float  g_totalH[TT*2*BB*HH];  // [t][dir][b][j]  coalesced for the rnn store
__device__ float  g_partial[VBLK*NROWS]; // per v-block partial sum-of-exp (deterministic)
__device__ float  g_rowstat[NROWS];      // log(sum exp) per row (natural log)
__device__ float  g_Wt1[16*VV];          // tiled tf32 W * log2e, 2 MB (single copy)
__device__ int    g_cnt[64];             // per slice: phase-A completion counters
__device__ int    g_flag[64];            // per slice: rowstat-ready flags
__device__ int    g_sliceCnt[64];        // per slice: rnn chain completion (16 = ready)
__device__ int    g_wflag[32];           // per bx: W region prepped
// pair-permuted tile layout: v-pair P = v>>4, u = v&15.
//   tile = 2P + ((u>>1)&1),  n = ((u>>2)<<1) | (u&1)
//   pos  = tile*128 + n*16 + (k&3)*4 + (k>>2)
// thread (g=n-group, q) then owns 4 CONSECUTIVE v = P*16 + 4q + {0,1,2,3}
// from the two tiles of a pair -> phase B emits STG.128.

// tf32 round (rna)
__device__ __forceinline__ unsigned tf32_of(float x) {
    unsigned r;
    asm("cvt.rna.tf32.f32 %0, %1;" : "=r"(r) : "f"(x));
    return r;
}
__device__ __forceinline__ float ex2(float x) {
    float r; asm("ex2.approx.f32 %0, %1;" : "=f"(r) : "f"(x)); return r;
}
__device__ __forceinline__ float rcp(float x) {
    float r; asm("rcp.approx.f32 %0, %1;" : "=f"(r) : "f"(x)); return r;
}

// m16n8k8 tf32 mma, D += A*B (C aliased to D)
__device__ __forceinline__ void mma_tf32(float& d0, float& d1, float& d2, float& d3,
                                         unsigned a0, unsigned a1, unsigned a2, unsigned a3,
                                         unsigned b0, unsigned b1) {
    asm("mma.sync.aligned.m16n8k8.row.col.f32.tf32.tf32.f32 "
        "{%0,%1,%2,%3}, {%4,%5,%6,%7}, {%8,%9}, {%0,%1,%2,%3};"
        : "+f"(d0), "+f"(d1), "+f"(d2), "+f"(d3)
        : "r"(a0), "r"(a1), "r"(a2), "r"(a3), "r"(b0), "r"(b1));
}

// blockIdx.y -> t-slice permutation. Slice y ready at rnn step max(16y+15, 1023-16y):
// middle slices earliest. ylin=0 (contains the 16 rnn-carrier blocks) gets y=0
// (ready last); ylin>=1 get middle-out slices so the earliest-scheduled
// non-carrier blocks wait the least. (ylin==1 blocks also prep W first.)
__device__ __forceinline__ int slice_of(int ylin) {
    if (ylin == 0) return 0;
    int j = ylin - 1;                       // 0..62
    return (j & 1) ? (32 - ((j + 1) >> 1)) : (32 + (j >> 1));  // 32,31,33,30,...,1,63
}

// ---------------- kernel 1: embedding gather + x-projections + sync reset -----
// stores xp' = -log2e * (e@Wx + bx + bh) so the rnn uses ex2 directly
__global__ void k_embed(const int* __restrict__ x, const float* __restrict__ emb,
                        const float* __restrict__ Wx1, const float* __restrict__ bx1,
                        const float* __restrict__ bh1,
                        const float* __restrict__ Wx2, const float* __restrict__ bx2,
                        const float* __restrict__ bh2) {
    int tid = blockIdx.x * blockDim.x + threadIdx.x;   // (t,b) flat
    if (blockIdx.x == 0 && threadIdx.x < 64) {         // reset sync state per replay
        g_cnt[threadIdx.x] = 0;
        g_flag[threadIdx.x] = 0;
        g_sliceCnt[threadIdx.x] = 0;
        if (threadIdx.x < 32) g_wflag[threadIdx.x] = 0;
    }
    if (tid >= NROWS) return;
    int idx = x[tid];
    const float4* em = (const float4*)(emb + (size_t)idx * EE);
    float e[EE];
    #pragma unroll
    for (int q = 0; q < 8; q++) {
        float4 v = __ldg(em + q);
        e[4*q] = v.x; e[4*q+1] = v.y; e[4*q+2] = v.z; e[4*q+3] = v.w;
    }
    #pragma unroll
    for (int j = 0; j < HH; j++) {
        float s1 = bx1[j] + bh1[j];
        float s2 = bx2[j] + bh2[j];
        #pragma unroll
        for (int k = 0; k < EE; k++) {
            s1 = fmaf(e[k], __ldg(Wx1 + k*HH + j), s1);
            s2 = fmaf(e[k], __ldg(Wx2 + k*HH + j), s2);
        }
        g_xp[tid*HH + j] = s1 * (-LOG2E);
        g_xp[TT*BB*HH + tid*HH + j] = s2 * (-LOG2E);
    }
}

// ---------------- rnn chain (runs inside carrier blocks of the fused kernel) ---
// Threads 0..7 of the block; chain id c in 0..15. h exchange via double-buffered
// SMEM (1 STS + 1 syncwarp + 2 LDS.128 per step instead of 8 SHFLs -> far less
// MIO queueing on the lone active warp).
// Signals g_sliceCnt[t>>4] after finishing each 16-t slice (release ordering).
__device__ void run_chain(int c, int j, float* sh,
                          const float* __restrict__ Wh1,
                          const float* __restrict__ Wh2) {
    int dir = c >> 3, b = c & 7;
    const float* Wh = dir ? Wh2 : Wh1;
    float w[HH];
    #pragma unroll
    for (int k = 0; k < HH; k++) w[k] = __ldg(Wh + k*HH + j) * (-LOG2E);

    const float* xp = g_xp + dir * (TT*BB*HH);
    float h = 0.f;

    // depth-4 prefetch ring
    float pf[4];
    #pragma unroll
    for (int p = 0; p < 4; p++) {
        int t = dir ? (TT - 1 - p) : p;
        pf[p] = __ldg(xp + (t*BB + b) * HH + j);
    }

    #pragma unroll 4
    for (int s = 0; s < TT; s++) {
        int slot = s & 3;
        float xv = pf[slot];
        if (s + 4 < TT) {
            int t4 = dir ? (TT - 1 - (s + 4)) : (s + 4);
            pf[slot] = __ldg(xp + (t4*BB + b) * HH + j);
        }
        int t = dir ? (TT - 1 - s) : s;
        // emit pre-update hidden state: [t][dir][b][j]
        g_totalH[t*128 + dir*64 + b*8 + j] = h;
        // slice boundary: dir0 ascending completes at t%16==15, dir1 at t%16==0
        if ((t & 15) == (dir ? 0 : 15)) {
            __syncwarp(0xffu);
            __threadfence();                 // release totalH stores
            if (j == 0) atomicAdd(&g_sliceCnt[t >> 4], 1);
        }
        // exchange h via smem (double-buffered by step parity)
        float* buf = sh + (s & 1) * 8;
        buf[j] = h;
        __syncwarp(0xffu);
        float4 lo = *(const float4*)(buf);       // broadcast LDS.128
        float4 hi = *(const float4*)(buf + 4);
        float t0 = fmaf(lo.y, w[1], lo.x * w[0]);
        float t1 = fmaf(lo.w, w[3], lo.z * w[2]);
        float t2 = fmaf(hi.y, w[5], hi.x * w[4]);
        float t3 = fmaf(hi.w, w[7], hi.z * w[6]);
        float z  = xv + ((t0 + t1) + (t2 + t3));
        h = rcp(1.f + ex2(z));              // sigmoid
    }
}

// ---------------- fused kernel: W-prep + rnn carriers + GEMM + stat + output ---
// Grid (VBLK, 64), block 256.
//  * blocks (bx, ylin==1): prep W region bx (pair-permuted tf32*log2e), flag it.
//  * blocks (bx<16, ylin==0): warp 0 lanes 0..7 run one rnn chain each.
//  * all blocks: spin on W flag + slice readiness, then R13/R14 flow:
//    phase A (2^d sums -> partials -> last-block stat -> flag), spin, phase B
//    (recompute, store d*ln2 - st with STG.128).
__global__ __launch_bounds__(256) void k_fused(float* __restrict__ out,
                                               const float* __restrict__ Wo,
                                               const float* __restrict__ Wh1,
                                               const float* __restrict__ Wh2) {
    __shared__ __align__(16) float sh_h[16];   // rnn h exchange (carriers only)

    // ---------------- W prep section (ylin == 1) ----------------
    if (blockIdx.y == 1) {
        int vbase = blockIdx.x * 1280;         // this bx's v range (160 tiles)
        #pragma unroll 1
        for (int k = 0; k < 16; k++) {
            #pragma unroll
            for (int it = 0; it < 5; it++) {
                int v = vbase + it * 256 + threadIdx.x;
                float x = __ldg(Wo + (size_t)k * VV + v);
                int P = v >> 4, u = v & 15;
                int tile = 2*P + ((u >> 1) & 1);
                int n = ((u >> 2) << 1) | (u & 1);
                int pos = tile*128 + n*16 + (k & 3)*4 + (k >> 2);
                g_Wt1[pos] = __uint_as_float(tf32_of(x * LOG2E));
            }
        }
        __threadfence();                       // publish W region
        __syncthreads();
        if (threadIdx.x == 0) atomicExch(&g_wflag[blockIdx.x], 1);
    }

    // ---------------- rnn carrier section (ylin == 0, bx < 16) ----------------
    if (blockIdx.y == 0 && blockIdx.x < 16) {
        if (threadIdx.x < 8)
            run_chain(blockIdx.x, threadIdx.x, sh_h, Wh1, Wh2);
        __syncthreads();                   // park warps 1..7 while warp 0 chains
    }

    int lane = threadIdx.x & 31, w = threadIdx.x >> 5;
    int g = lane >> 2, q = lane & 3;
    int y = slice_of(blockIdx.y);
    int rowBase = y * 128 + w * 16;

    // ---------------- wait for W region + this block's t-slice ----------------
    if (threadIdx.x == 0) {
        while (atomicAdd(&g_wflag[blockIdx.x], 0) == 0) __nanosleep(100);
        while (atomicAdd(&g_sliceCnt[y], 0) < 16) __nanosleep(100);
    }
    __syncthreads();
    __threadfence();                       // acquire totalH + W

    // A fragments, loaded once. jj: row g+(jj&1)*8, col q+(jj>>1)*4
    unsigned ah[2][4];
    #pragma unroll
    for (int kt = 0; kt < 2; kt++) {
        #pragma unroll
        for (int jj = 0; jj < 4; jj++) {
            int r = g + (jj & 1) * 8;
            int k = kt * 8 + q + ((jj >> 1) ? 4 : 0);
            int grow = rowBase + r, t = grow >> 3, b = grow & 7;
            ah[kt][jj] = tf32_of(g_totalH[t*128 + (k >> 3)*64 + b*8 + (k & 7)]);
        }
    }

    int vt0 = blockIdx.x * (VITER * 16);   // first v-tile index of this block
    const float4* Bbase = (const float4*)(g_Wt1 + (size_t)vt0 * 128 + g * 16 + q * 4);

    // ---------------- phase A: sums ----------------
    {
        float sum0 = 0.f, sum1 = 0.f;
        const float4* Bt = Bbase;
        for (int it = 0; it < VITER; it++) {
            #pragma unroll
            for (int pr = 0; pr < 8; pr++) {       // 8 tile-pairs = 128 v per iter
                float4 B0 = __ldg(Bt);             // tile 2P
                float4 B1 = __ldg(Bt + 32);        // tile 2P+1
                Bt += 64;
                unsigned b000 = __float_as_uint(B0.x), b001 = __float_as_uint(B0.y);
                unsigned b010 = __float_as_uint(B0.z), b011 = __float_as_uint(B0.w);
                unsigned b100 = __float_as_uint(B1.x), b101 = __float_as_uint(B1.y);
                unsigned b110 = __float_as_uint(B1.z), b111 = __float_as_uint(B1.w);

                float e0 = 0.f, e1 = 0.f, e2 = 0.f, e3 = 0.f;
                mma_tf32(e0,e1,e2,e3, ah[0][0],ah[0][1],ah[0][2],ah[0][3], b000,b001);
                mma_tf32(e0,e1,e2,e3, ah[1][0],ah[1][1],ah[1][2],ah[1][3], b010,b011);
                float f0 = 0.f, f1 = 0.f, f2 = 0.f, f3 = 0.f;
                mma_tf32(f0,f1,f2,f3, ah[0][0],ah[0][1],ah[0][2],ah[0][3], b100,b101);
                mma_tf32(f0,f1,f2,f3, ah[1][0],ah[1][1],ah[1][2],ah[1][3], b110,b111);

                sum0 += (ex2(e0) + ex2(e1)) + (ex2(f0) + ex2(f1));
                sum1 += (ex2(e2) + ex2(e3)) + (ex2(f2) + ex2(f3));
            }
        }
        // reduce across the 4 q-lanes sharing each row-group g
        sum0 += __shfl_xor_sync(0xffffffffu, sum0, 1);
        sum0 += __shfl_xor_sync(0xffffffffu, sum0, 2);
        sum1 += __shfl_xor_sync(0xffffffffu, sum1, 1);
        sum1 += __shfl_xor_sync(0xffffffffu, sum1, 2);
        if (q == 0) {
            float* p = g_partial + (size_t)blockIdx.x * NROWS + rowBase;
            p[g    ] = sum0;
            p[g + 8] = sum1;
        }
    }

    // ---------------- stat by last-arriving block of this slice ----------------
    __shared__ bool isLast;
    __threadfence();                       // publish partials (release)
    __syncthreads();
    if (threadIdx.x == 0) {
        int old = atomicAdd(&g_cnt[y], 1);
        isLast = (old == VBLK - 1);
    }
    __syncthreads();
    if (isLast) {
        int r0 = y * 128;
        for (int r = threadIdx.x; r < 128; r += 256) {
            float s = 0.f;
            #pragma unroll
            for (int i = 0; i < VBLK; i++)
                s += __ldcg(g_partial + (size_t)i * NROWS + r0 + r);
            g_rowstat[r0 + r] = logf(s);
        }
        __threadfence();                   // publish rowstat before flag
        __syncthreads();
        if (threadIdx.x == 0) atomicExch(&g_flag[y], 1);
    }

    // ---------------- spin until rowstat ready ----------------
    if (threadIdx.x == 0) {
        while (atomicAdd(&g_flag[y], 0) == 0) __nanosleep(200);
    }
    __syncthreads();
    __threadfence();                       // acquire

    float st0 = __ldcg(g_rowstat + rowBase + g);
    float st1 = __ldcg(g_rowstat + rowBase + g + 8);

    // ---------------- phase B: outputs ----------------
    {
        const float4* Bt = Bbase;
        size_t vc = (size_t)vt0 * 8 + q * 4;   // P0*16 + 4q
        float* op0 = out + (size_t)(rowBase + g    ) * VV + vc;
        float* op1 = out + (size_t)(rowBase + g + 8) * VV + vc;

        for (int it = 0; it < VITER; it++) {
            #pragma unroll
            for (int pr = 0; pr < 8; pr++) {
                float4 B0 = __ldg(Bt);
                float4 B1 = __ldg(Bt + 32);
                Bt += 64;
                unsigned b000 = __float_as_uint(B0.x), b001 = __float_as_uint(B0.y);
                unsigned b010 = __float_as_uint(B0.z), b011 = __float_as_uint(B0.w);
                unsigned b100 = __float_as_uint(B1.x), b101 = __float_as_uint(B1.y);
                unsigned b110 = __float_as_uint(B1.z), b111 = __float_as_uint(B1.w);

                float e0 = 0.f, e1 = 0.f, e2 = 0.f, e3 = 0.f;
                mma_tf32(e0,e1,e2,e3, ah[0][0],ah[0][1],ah[0][2],ah[0][3], b000,b001);
                mma_tf32(e0,e1,e2,e3, ah[1][0],ah[1][1],ah[1][2],ah[1][3], b010,b011);
                float f0 = 0.f, f1 = 0.f, f2 = 0.f, f3 = 0.f;
                mma_tf32(f0,f1,f2,f3, ah[0][0],ah[0][1],ah[0][2],ah[0][3], b100,b101);
                mma_tf32(f0,f1,f2,f3, ah[1][0],ah[1][1],ah[1][2],ah[1][3], b110,b111);

                // natural logit = d * ln2 ; output = logit - logsumexp
                float4 o0 = make_float4(fmaf(e0, LN2, -st0), fmaf(e1, LN2, -st0),
                                        fmaf(f0, LN2, -st0), fmaf(f1, LN2, -st0));
                float4 o1 = make_float4(fmaf(e2, LN2, -st1), fmaf(e3, LN2, -st1),
                                        fmaf(f2, LN2, -st1), fmaf(f3, LN2, -st1));
                __stcs((float4*)op0, o0);
                __stcs((float4*)op1, o1);
                op0 += 16; op1 += 16;
            }
        }
    }
}

// ---------------- launch ----------------
extern "C" void kernel_launch(void* const* d_in, const int* in_sizes, int n_in,
                              void* d_out, int out_size) {
    const int*   x   = (const int*)  d_in[0];
    const float* emb = (const float*)d_in[1];
    const float* Wx1 = (const float*)d_in[2];
    const float* bx1 = (const float*)d_in[3];
    const float* Wh1 = (const float*)d_in[4];
    const float* bh1 = (const float*)d_in[5];
    const float* Wx2 = (const float*)d_in[6];
    const float* bx2 = (const float*)d_in[7];
    const float* Wh2 = (const float*)d_in[8];
    const float* bh2 = (const float*)d_in[9];
    const float* Wo  = (const float*)d_in[10];
    float* out = (float*)d_out;

    k_embed<<<(NROWS + 255)/256, 256>>>(x, emb, Wx1, bx1, bh1, Wx2, bx2, bh2);
    dim3 grd(VBLK, NROWS/128), blk(256);
    k_fused<<<grd, blk>>>(out, Wo, Wh1, Wh2);
}